// round 4
// baseline (speedup 1.0000x reference)
#include <cuda_runtime.h>
#include <math.h>

// DifferentiableICP: B=32 batches, N=M=2048 points, 5 soft-ICP iterations.
//
// Cost is dominated by B*N*M*ITER = 671M softmax cells. Design:
//  - logit = 2*st.t - |t|^2  (row constants cancel in softmax; no max pass;
//    bounded |logit| keeps fp32 safe: max ~55 -> exp<=1e24, denom >= ~0.5)
//  - fold log2e into precomputed target constants so inner loop is
//    2 FFMA + ex2.approx + FADD + 2 FFMA + 1 LDS.128 = 7 issue slots,
//    1 MUFU/cell  => MUFU-bound at rt 8/SMSP. Chip: 2368 exp/cyc -> ~150us.
//  - 2x2 SVD R=V@U^T == orthogonal polar factor of H^T (closed form).
//  - Per-iteration: big kernel -> per-chunk partials; tiny kernel -> fixed-order
//    reduce + transform update. 11 launches total, all graph-capturable.

#define BB 32
#define NN 2048
#define MM 2048
#define ITERS 5
#define CHUNKS 32            // chunks per batch
#define ROWS_PER_CTA (NN / CHUNKS)   // 64
#define THREADS ROWS_PER_CTA          // 64, one row per thread

// Scratch (allocation-free rule: __device__ globals)
__device__ float4 g_tprep[BB][MM];     // (u, v, w, 0) per target point, 2MB
__device__ float  g_T[BB][4];          // (cos, sin, tx, ty) current transform
__device__ float  g_part[BB][CHUNKS][8];

// ---------------------------------------------------------------------------
// Init: precompute log2e-folded target constants + initial transform.
// ---------------------------------------------------------------------------
__global__ void icp_init_kernel(const float* __restrict__ target,
                                const float* __restrict__ init_t) {
    int g = blockIdx.x * blockDim.x + threadIdx.x;
    if (g < BB * MM) {
        int b = g / MM, m = g % MM;
        float tx = target[(size_t)g * 2 + 0];
        float ty = target[(size_t)g * 2 + 1];
        const float L2E = 1.4426950408889634f;
        float4 v;
        v.x = 2.0f * L2E * tx;
        v.y = 2.0f * L2E * ty;
        v.z = -L2E * (tx * tx + ty * ty);
        v.w = 0.0f;
        g_tprep[b][m] = v;
    }
    if (g < BB) {
        float th = init_t[g * 3 + 0];
        g_T[g][0] = cosf(th);
        g_T[g][1] = sinf(th);
        g_T[g][2] = init_t[g * 3 + 1];
        g_T[g][3] = init_t[g * 3 + 2];
    }
}

// ---------------------------------------------------------------------------
// Main per-iteration kernel: soft correspondences + per-chunk partial sums.
// grid = BB*CHUNKS (1024 CTAs), block = 64 threads, 32KB smem -> ~7 CTAs/SM,
// single wave, MUFU-bound mainloop.
// ---------------------------------------------------------------------------
__global__ void __launch_bounds__(THREADS, 7)
icp_iter_kernel(const float* __restrict__ source) {
    __shared__ float4 sm[MM];            // 32 KB target constants
    __shared__ float  red[2][8];

    const int b     = blockIdx.x >> 5;   // / CHUNKS
    const int chunk = blockIdx.x & 31;   // % CHUNKS
    const int tid   = threadIdx.x;

    // Stage target constants into smem (coalesced)
    const float4* tp = &g_tprep[b][0];
    #pragma unroll 4
    for (int i = tid; i < MM; i += THREADS) sm[i] = tp[i];

    // Current transform (uniform across CTA)
    const float c  = g_T[b][0];
    const float s  = g_T[b][1];
    const float tx = g_T[b][2];
    const float ty = g_T[b][3];

    // This thread's source row -> st = R*s + t
    const int row = chunk * ROWS_PER_CTA + tid;
    const float2 sv = reinterpret_cast<const float2*>(source)[(size_t)b * NN + row];
    const float sx = c * sv.x - s * sv.y + tx;
    const float sy = s * sv.x + c * sv.y + ty;

    __syncthreads();

    // Single-pass softmax-weighted target average.
    float se = 0.0f, au = 0.0f, av = 0.0f;
    #pragma unroll 8
    for (int m = 0; m < MM; ++m) {
        float4 t = sm[m];
        float y = fmaf(sx, t.x, t.z);
        y = fmaf(sy, t.y, y);
        float e;
        asm("ex2.approx.ftz.f32 %0, %1;" : "=f"(e) : "f"(y));  // weight (unnormalized)
        se += e;
        au = fmaf(e, t.x, au);   // sum e * (2*log2e*tx)
        av = fmaf(e, t.y, av);   // sum e * (2*log2e*ty)
    }
    const float KINV = 0.34657359027997264f;  // ln(2)/2  (undo the folded 2*log2e)
    const float inv  = KINV / se;
    const float tcx = au * inv;
    const float tcy = av * inv;

    // Partial sums for centroids + cross-covariance:
    // [ sum st.x, sum st.y, sum tc.x, sum tc.y, sum stx*tcx, stx*tcy, sty*tcx, sty*tcy ]
    float p[8] = {sx, sy, tcx, tcy, sx * tcx, sx * tcy, sy * tcx, sy * tcy};

    // Deterministic warp butterfly reduce
    #pragma unroll
    for (int off = 16; off; off >>= 1)
        #pragma unroll
        for (int k = 0; k < 8; ++k)
            p[k] += __shfl_xor_sync(0xFFFFFFFFu, p[k], off);

    const int wid = tid >> 5, lane = tid & 31;
    if (lane == 0)
        #pragma unroll
        for (int k = 0; k < 8; ++k) red[wid][k] = p[k];
    __syncthreads();
    if (tid == 0) {
        #pragma unroll
        for (int k = 0; k < 8; ++k)
            g_part[b][chunk][k] = red[0][k] + red[1][k];
    }
}

// ---------------------------------------------------------------------------
// Per-iteration update: reduce 32 chunk partials, closed-form 2x2 SVD
// (polar factor of H^T), compose transform. Writes output on final iter.
// grid = BB blocks x 32 threads.
// ---------------------------------------------------------------------------
__global__ void icp_update_kernel(float* __restrict__ out, int final_iter) {
    const int b = blockIdx.x;
    const int t = threadIdx.x;   // 32 threads = 32 chunks

    float p[8];
    #pragma unroll
    for (int k = 0; k < 8; ++k) p[k] = g_part[b][t][k];
    #pragma unroll
    for (int off = 16; off; off >>= 1)
        #pragma unroll
        for (int k = 0; k < 8; ++k)
            p[k] += __shfl_xor_sync(0xFFFFFFFFu, p[k], off);

    if (t == 0) {
        const float invN = 1.0f / (float)NN;
        const float csx = p[0] * invN, csy = p[1] * invN;   // centroid_s
        const float ctx = p[2] * invN, cty = p[3] * invN;   // centroid_t(corr)

        // H = sum (st-cs)(tc-ct)^T = C - S1*S2^T / N
        const float h00 = p[4] - p[0] * p[2] * invN;
        const float h01 = p[5] - p[0] * p[3] * invN;
        const float h10 = p[6] - p[1] * p[2] * invN;
        const float h11 = p[7] - p[1] * p[3] * invN;

        // R_delta = V @ U^T (SVD of H) == orthogonal polar factor of H^T.
        // Closed form via rotation/reflection split of A = H^T:
        const float E  = 0.5f * (h00 + h11);
        const float F  = 0.5f * (h00 - h11);
        const float G  = 0.5f * (h01 + h10);
        const float Hh = 0.5f * (h01 - h10);
        const float det = h00 * h11 - h01 * h10;   // = q^2 - r^2

        float r00, r01, r10, r11;
        if (det >= 0.0f) {          // rotation branch
            float iq = rsqrtf(E * E + Hh * Hh);
            r00 =  E * iq;  r01 = -Hh * iq;
            r10 = Hh * iq;  r11 =  E * iq;
        } else {                     // reflection branch (matches V@U^T w/o det fix)
            float ir = rsqrtf(F * F + G * G);
            r00 =  F * ir;  r01 =  G * ir;
            r10 =  G * ir;  r11 = -F * ir;
        }

        // delta_theta = atan2(r10, r00); vec2mat uses cos/sin of it:
        const float ih = rsqrtf(r00 * r00 + r10 * r10);
        const float cD = r00 * ih;
        const float sD = r10 * ih;
        // t_delta uses the FULL R_delta (incl. possible reflection), per reference
        const float tDx = ctx - (r00 * csx + r01 * csy);
        const float tDy = cty - (r10 * csx + r11 * csy);

        // T_new = vec2mat(delta) @ T_old
        const float c  = g_T[b][0], s  = g_T[b][1];
        const float tx = g_T[b][2], ty = g_T[b][3];
        const float c2  = cD * c - sD * s;
        const float s2  = sD * c + cD * s;
        const float tx2 = cD * tx - sD * ty + tDx;
        const float ty2 = sD * tx + cD * ty + tDy;
        g_T[b][0] = c2; g_T[b][1] = s2; g_T[b][2] = tx2; g_T[b][3] = ty2;

        if (final_iter) {
            out[b * 3 + 0] = atan2f(s2, c2);
            out[b * 3 + 1] = tx2;
            out[b * 3 + 2] = ty2;
        }
    }
}

// ---------------------------------------------------------------------------
extern "C" void kernel_launch(void* const* d_in, const int* in_sizes, int n_in,
                              void* d_out, int out_size) {
    const float* source = (const float*)d_in[0];   // (32, 2048, 2)
    const float* target = (const float*)d_in[1];   // (32, 2048, 2)
    const float* init_t = (const float*)d_in[2];   // (32, 3)
    float* out = (float*)d_out;                    // (32, 3)

    icp_init_kernel<<<(BB * MM + 255) / 256, 256>>>(target, init_t);
    for (int it = 0; it < ITERS; ++it) {
        icp_iter_kernel<<<BB * CHUNKS, THREADS>>>(source);
        icp_update_kernel<<<BB, 32>>>(out, it == ITERS - 1 ? 1 : 0);
    }
}

// round 5
// speedup vs baseline: 1.1730x; 1.1730x over previous
#include <cuda_runtime.h>
#include <math.h>

// DifferentiableICP: B=32, N=M=2048, 5 soft-ICP iterations.
// R4: packed f32x2 FMA mainloop (halves fma/issue cost -> MUFU.EX2-bound at
//     8 cyc/warp-cell/SMSP) + 4-way M-split (2048 -> 8192 warps, occ 16%->60%+).
// EX2 roofline: 671M exps / (148*4 SMSP / 8 cyc) ~ 28us/iter.

#define BB 32
#define NN 2048
#define MM 2048
#define ITERS 5
#define CHUNKS 32                    // chunks per batch (rows)
#define ROWS_PER_CTA (NN / CHUNKS)   // 64
#define MSPLIT 4                     // threads per row along M
#define TPB (ROWS_PER_CTA * MSPLIT)  // 256
#define NPAIR (MM / 2)               // 1024 target pairs
#define SEGPAIRS (NPAIR / MSPLIT)    // 256 pairs per segment

typedef unsigned long long ull;

// Scratch (allocation-free rule: __device__ globals)
__device__ ull   g_u2[BB][NPAIR];   // packed (2*log2e*tx) pairs
__device__ ull   g_v2[BB][NPAIR];   // packed (2*log2e*ty) pairs
__device__ ull   g_w2[BB][NPAIR];   // packed (-log2e*|t|^2) pairs
__device__ float g_T[BB][4];        // (cos, sin, tx, ty)
__device__ float g_part[BB][CHUNKS][8];

// ---- packed f32x2 helpers (PTX-only; ptxas never auto-fuses FFMA2) --------
__device__ __forceinline__ ull fma2(ull a, ull b, ull c) {
    ull d; asm("fma.rn.f32x2 %0, %1, %2, %3;" : "=l"(d) : "l"(a), "l"(b), "l"(c));
    return d;
}
__device__ __forceinline__ ull add2(ull a, ull b) {
    ull d; asm("add.rn.f32x2 %0, %1, %2;" : "=l"(d) : "l"(a), "l"(b));
    return d;
}
__device__ __forceinline__ ull pack2(float lo, float hi) {
    ull d; asm("mov.b64 %0, {%1, %2};" : "=l"(d) : "f"(lo), "f"(hi));
    return d;
}
__device__ __forceinline__ void unpack2(ull v, float& lo, float& hi) {
    asm("mov.b64 {%0, %1}, %2;" : "=f"(lo), "=f"(hi) : "l"(v));
}
__device__ __forceinline__ float ex2f(float x) {
    float e; asm("ex2.approx.ftz.f32 %0, %1;" : "=f"(e) : "f"(x));
    return e;
}

// ---------------------------------------------------------------------------
// Init: paired, log2e-folded target constants + initial transform.
// ---------------------------------------------------------------------------
__global__ void icp_init_kernel(const float* __restrict__ target,
                                const float* __restrict__ init_t) {
    int g = blockIdx.x * blockDim.x + threadIdx.x;
    if (g < BB * NPAIR) {
        int b = g >> 10, p = g & (NPAIR - 1);
        float4 f = reinterpret_cast<const float4*>(target)[(size_t)b * NPAIR + p];
        const float L2E = 1.4426950408889634f;
        g_u2[b][p] = pack2(2.0f * L2E * f.x, 2.0f * L2E * f.z);
        g_v2[b][p] = pack2(2.0f * L2E * f.y, 2.0f * L2E * f.w);
        g_w2[b][p] = pack2(-L2E * (f.x * f.x + f.y * f.y),
                           -L2E * (f.z * f.z + f.w * f.w));
    }
    if (g < BB) {
        float th = init_t[g * 3 + 0];
        g_T[g][0] = cosf(th);
        g_T[g][1] = sinf(th);
        g_T[g][2] = init_t[g * 3 + 1];
        g_T[g][3] = init_t[g * 3 + 2];
    }
}

// ---------------------------------------------------------------------------
// Main per-iteration kernel. grid = BB*CHUNKS = 1024 CTAs, block = 256.
// Thread t: row = chunk*64 + (t&63), segment = t>>6 covers 256 target pairs.
// ---------------------------------------------------------------------------
__global__ void __launch_bounds__(TPB)
icp_iter_kernel(const float* __restrict__ source) {
    __shared__ ull    sU[NPAIR], sV[NPAIR], sW[NPAIR];  // 24 KB
    __shared__ float4 sredA[MSPLIT - 1][ROWS_PER_CTA];  // seg partials
    __shared__ float  red2[2][8];

    const int b     = blockIdx.x >> 5;
    const int chunk = blockIdx.x & 31;
    const int tid   = threadIdx.x;
    const int r     = tid & (ROWS_PER_CTA - 1);
    const int seg   = tid >> 6;

    // Stage paired target constants (coalesced 8B loads)
    for (int i = tid; i < NPAIR; i += TPB) {
        sU[i] = g_u2[b][i];
        sV[i] = g_v2[b][i];
        sW[i] = g_w2[b][i];
    }

    // Current transform (uniform)
    const float c  = g_T[b][0];
    const float s  = g_T[b][1];
    const float tx = g_T[b][2];
    const float ty = g_T[b][3];

    // st = R*source + t for this thread's row
    const int row = chunk * ROWS_PER_CTA + r;
    const float2 sv = reinterpret_cast<const float2*>(source)[(size_t)b * NN + row];
    const float sx = c * sv.x - s * sv.y + tx;
    const float sy = s * sv.x + c * sv.y + ty;
    const ull sx2 = pack2(sx, sx);
    const ull sy2 = pack2(sy, sy);

    __syncthreads();

    // Packed single-pass softmax-weighted sums over this segment.
    ull se2 = 0ull, au2 = 0ull, av2 = 0ull;
    const int p0 = seg * SEGPAIRS;
    #pragma unroll 4
    for (int p = p0; p < p0 + SEGPAIRS; ++p) {
        ull u2 = sU[p];
        ull v2 = sV[p];
        ull w2 = sW[p];
        ull y2 = fma2(sx2, u2, w2);
        y2 = fma2(sy2, v2, y2);
        float y0, y1; unpack2(y2, y0, y1);
        ull e2 = pack2(ex2f(y0), ex2f(y1));
        se2 = add2(se2, e2);
        au2 = fma2(e2, u2, au2);
        av2 = fma2(e2, v2, av2);
    }
    float a, bb2;
    unpack2(se2, a, bb2); float se = a + bb2;
    unpack2(au2, a, bb2); float au = a + bb2;
    unpack2(av2, a, bb2); float av = a + bb2;

    // Combine M-segments per row (fixed order: seg1+seg2+seg3 -> deterministic)
    if (seg > 0) sredA[seg - 1][r] = make_float4(se, au, av, 0.0f);
    __syncthreads();

    if (seg == 0) {
        #pragma unroll
        for (int k = 0; k < MSPLIT - 1; ++k) {
            float4 f = sredA[k][r];
            se += f.x; au += f.y; av += f.z;
        }
        const float KINV = 0.34657359027997264f;  // ln(2)/2 (undo folded 2*log2e)
        const float inv = KINV / se;
        const float tcx = au * inv;
        const float tcy = av * inv;

        // Partials: [ sum st.x, st.y, tc.x, tc.y, stx*tcx, stx*tcy, sty*tcx, sty*tcy ]
        float p[8] = {sx, sy, tcx, tcy, sx * tcx, sx * tcy, sy * tcx, sy * tcy};

        #pragma unroll
        for (int off = 16; off; off >>= 1)
            #pragma unroll
            for (int k = 0; k < 8; ++k)
                p[k] += __shfl_xor_sync(0xFFFFFFFFu, p[k], off);

        const int wid = tid >> 5, lane = tid & 31;  // warps 0,1 only here
        if (lane == 0)
            #pragma unroll
            for (int k = 0; k < 8; ++k) red2[wid][k] = p[k];
    }
    __syncthreads();
    if (tid == 0) {
        #pragma unroll
        for (int k = 0; k < 8; ++k)
            g_part[b][chunk][k] = red2[0][k] + red2[1][k];
    }
}

// ---------------------------------------------------------------------------
// Per-iteration update: reduce 32 chunk partials, closed-form 2x2 SVD
// (polar factor of H^T), compose transform. grid = BB x 32 threads.
// ---------------------------------------------------------------------------
__global__ void icp_update_kernel(float* __restrict__ out, int final_iter) {
    const int b = blockIdx.x;
    const int t = threadIdx.x;

    float p[8];
    #pragma unroll
    for (int k = 0; k < 8; ++k) p[k] = g_part[b][t][k];
    #pragma unroll
    for (int off = 16; off; off >>= 1)
        #pragma unroll
        for (int k = 0; k < 8; ++k)
            p[k] += __shfl_xor_sync(0xFFFFFFFFu, p[k], off);

    if (t == 0) {
        const float invN = 1.0f / (float)NN;
        const float csx = p[0] * invN, csy = p[1] * invN;
        const float ctx = p[2] * invN, cty = p[3] * invN;

        const float h00 = p[4] - p[0] * p[2] * invN;
        const float h01 = p[5] - p[0] * p[3] * invN;
        const float h10 = p[6] - p[1] * p[2] * invN;
        const float h11 = p[7] - p[1] * p[3] * invN;

        // R_delta = V @ U^T (SVD of H) == orthogonal polar factor of H^T.
        const float E  = 0.5f * (h00 + h11);
        const float F  = 0.5f * (h00 - h11);
        const float G  = 0.5f * (h01 + h10);
        const float Hh = 0.5f * (h01 - h10);
        const float det = h00 * h11 - h01 * h10;

        float r00, r01, r10, r11;
        if (det >= 0.0f) {           // rotation branch
            float iq = rsqrtf(E * E + Hh * Hh);
            r00 =  E * iq;  r01 = -Hh * iq;
            r10 = Hh * iq;  r11 =  E * iq;
        } else {                      // reflection branch
            float ir = rsqrtf(F * F + G * G);
            r00 =  F * ir;  r01 =  G * ir;
            r10 =  G * ir;  r11 = -F * ir;
        }

        const float ih = rsqrtf(r00 * r00 + r10 * r10);
        const float cD = r00 * ih;
        const float sD = r10 * ih;
        const float tDx = ctx - (r00 * csx + r01 * csy);
        const float tDy = cty - (r10 * csx + r11 * csy);

        const float c  = g_T[b][0], s  = g_T[b][1];
        const float tx = g_T[b][2], ty = g_T[b][3];
        const float c2  = cD * c - sD * s;
        const float s2  = sD * c + cD * s;
        const float tx2 = cD * tx - sD * ty + tDx;
        const float ty2 = sD * tx + cD * ty + tDy;
        g_T[b][0] = c2; g_T[b][1] = s2; g_T[b][2] = tx2; g_T[b][3] = ty2;

        if (final_iter) {
            out[b * 3 + 0] = atan2f(s2, c2);
            out[b * 3 + 1] = tx2;
            out[b * 3 + 2] = ty2;
        }
    }
}

// ---------------------------------------------------------------------------
extern "C" void kernel_launch(void* const* d_in, const int* in_sizes, int n_in,
                              void* d_out, int out_size) {
    const float* source = (const float*)d_in[0];   // (32, 2048, 2)
    const float* target = (const float*)d_in[1];   // (32, 2048, 2)
    const float* init_t = (const float*)d_in[2];   // (32, 3)
    float* out = (float*)d_out;                    // (32, 3)

    icp_init_kernel<<<(BB * NPAIR + 255) / 256, 256>>>(target, init_t);
    for (int it = 0; it < ITERS; ++it) {
        icp_iter_kernel<<<BB * CHUNKS, TPB>>>(source);
        icp_update_kernel<<<BB, 32>>>(out, it == ITERS - 1 ? 1 : 0);
    }
}

// round 6
// speedup vs baseline: 1.7064x; 1.4548x over previous
#include <cuda_runtime.h>
#include <math.h>

// DifferentiableICP: B=32, N=M=2048, 5 soft-ICP iterations.
// R5: register-tile 4 source rows per thread -> amortize LDS (3 loads per
//     4 row-pairs = 0.375 LSU/cell, was 1.5) and push the kernel onto the
//     irreducible MUFU.EX2 floor (~30us/iter: 4.2M warp-exps / 0.5 per cyc/SM).
// Layout: warp == M-segment (uniform LDS addresses -> broadcast),
//         lane l owns rows {l, l+32, l+64, l+96}. CTA=128 thr=128 rows x 4 segs.

#define BB 32
#define NN 2048
#define MM 2048
#define ITERS 5
#define CHUNKS 16                    // CTAs per batch
#define ROWS_PER_CTA (NN / CHUNKS)   // 128
#define RPT 4                        // rows per thread
#define MSPLIT 4                     // warps per CTA == M segments
#define TPB 128
#define NPAIR (MM / 2)               // 1024 packed target pairs
#define SEGPAIRS (NPAIR / MSPLIT)    // 256 pairs per segment

typedef unsigned long long ull;

// Scratch (allocation-free rule: __device__ globals)
__device__ ull   g_u2[BB][NPAIR];   // packed (2*log2e*tx) pairs
__device__ ull   g_v2[BB][NPAIR];   // packed (2*log2e*ty) pairs
__device__ ull   g_w2[BB][NPAIR];   // packed (-log2e*|t|^2) pairs
__device__ float g_T[BB][4];        // (cos, sin, tx, ty)
__device__ float g_part[BB][CHUNKS][8];

// ---- packed f32x2 helpers (PTX-only; ptxas never auto-fuses FFMA2) --------
__device__ __forceinline__ ull fma2(ull a, ull b, ull c) {
    ull d; asm("fma.rn.f32x2 %0, %1, %2, %3;" : "=l"(d) : "l"(a), "l"(b), "l"(c));
    return d;
}
__device__ __forceinline__ ull add2(ull a, ull b) {
    ull d; asm("add.rn.f32x2 %0, %1, %2;" : "=l"(d) : "l"(a), "l"(b));
    return d;
}
__device__ __forceinline__ ull pack2(float lo, float hi) {
    ull d; asm("mov.b64 %0, {%1, %2};" : "=l"(d) : "f"(lo), "f"(hi));
    return d;
}
__device__ __forceinline__ void unpack2(ull v, float& lo, float& hi) {
    asm("mov.b64 {%0, %1}, %2;" : "=f"(lo), "=f"(hi) : "l"(v));
}
__device__ __forceinline__ float ex2f(float x) {
    float e; asm("ex2.approx.ftz.f32 %0, %1;" : "=f"(e) : "f"(x));
    return e;
}

// ---------------------------------------------------------------------------
// Init: paired, log2e-folded target constants + initial transform.
// ---------------------------------------------------------------------------
__global__ void icp_init_kernel(const float* __restrict__ target,
                                const float* __restrict__ init_t) {
    int g = blockIdx.x * blockDim.x + threadIdx.x;
    if (g < BB * NPAIR) {
        int b = g >> 10, p = g & (NPAIR - 1);
        float4 f = reinterpret_cast<const float4*>(target)[(size_t)b * NPAIR + p];
        const float L2E = 1.4426950408889634f;
        g_u2[b][p] = pack2(2.0f * L2E * f.x, 2.0f * L2E * f.z);
        g_v2[b][p] = pack2(2.0f * L2E * f.y, 2.0f * L2E * f.w);
        g_w2[b][p] = pack2(-L2E * (f.x * f.x + f.y * f.y),
                           -L2E * (f.z * f.z + f.w * f.w));
    }
    if (g < BB) {
        float th = init_t[g * 3 + 0];
        g_T[g][0] = cosf(th);
        g_T[g][1] = sinf(th);
        g_T[g][2] = init_t[g * 3 + 1];
        g_T[g][3] = init_t[g * 3 + 2];
    }
}

// ---------------------------------------------------------------------------
// Main per-iteration kernel. grid = BB*CHUNKS = 512 CTAs, block = 128.
// Warp w == M-segment w (uniform LDS addresses -> broadcast, 1 wavefront).
// Lane l owns rows {l, l+32, l+64, l+96} of this CTA's 128-row chunk.
// ---------------------------------------------------------------------------
__global__ void __launch_bounds__(TPB)
icp_iter_kernel(const float* __restrict__ source) {
    __shared__ ull    sU[NPAIR], sV[NPAIR], sW[NPAIR];   // 24 KB
    __shared__ float4 sRow[MSPLIT - 1][ROWS_PER_CTA];    // 6 KB seg partials

    const int b     = blockIdx.x >> 4;
    const int chunk = blockIdx.x & 15;
    const int tid   = threadIdx.x;
    const int lane  = tid & 31;
    const int warp  = tid >> 5;          // == segment

    // Stage paired target constants (coalesced 8B loads)
    for (int i = tid; i < NPAIR; i += TPB) {
        sU[i] = g_u2[b][i];
        sV[i] = g_v2[b][i];
        sW[i] = g_w2[b][i];
    }

    // Current transform (uniform)
    const float c  = g_T[b][0];
    const float s  = g_T[b][1];
    const float tx = g_T[b][2];
    const float ty = g_T[b][3];

    // st = R*source + t for this thread's 4 rows
    float sx[RPT], sy[RPT];
    ull sx2[RPT], sy2[RPT];
    #pragma unroll
    for (int k = 0; k < RPT; ++k) {
        const int row = chunk * ROWS_PER_CTA + lane + 32 * k;
        const float2 sv = reinterpret_cast<const float2*>(source)[(size_t)b * NN + row];
        sx[k] = c * sv.x - s * sv.y + tx;
        sy[k] = s * sv.x + c * sv.y + ty;
        sx2[k] = pack2(sx[k], sx[k]);
        sy2[k] = pack2(sy[k], sy[k]);
    }

    __syncthreads();

    // Packed single-pass softmax-weighted sums: 3 LDS amortized over 4 rows.
    ull se2[RPT], au2[RPT], av2[RPT];
    #pragma unroll
    for (int k = 0; k < RPT; ++k) { se2[k] = 0ull; au2[k] = 0ull; av2[k] = 0ull; }

    const int p0 = warp * SEGPAIRS;
    #pragma unroll 2
    for (int p = p0; p < p0 + SEGPAIRS; ++p) {
        const ull u2 = sU[p];
        const ull v2 = sV[p];
        const ull w2 = sW[p];
        #pragma unroll
        for (int k = 0; k < RPT; ++k) {
            ull y2 = fma2(sx2[k], u2, w2);
            y2 = fma2(sy2[k], v2, y2);
            float y0, y1; unpack2(y2, y0, y1);
            const ull e2 = pack2(ex2f(y0), ex2f(y1));
            se2[k] = add2(se2[k], e2);
            au2[k] = fma2(e2, u2, au2[k]);
            av2[k] = fma2(e2, v2, av2[k]);
        }
    }

    // Horizontal add of the packed halves (fixed order: lo + hi)
    float se[RPT], au[RPT], av[RPT];
    #pragma unroll
    for (int k = 0; k < RPT; ++k) {
        float a0, a1;
        unpack2(se2[k], a0, a1); se[k] = a0 + a1;
        unpack2(au2[k], a0, a1); au[k] = a0 + a1;
        unpack2(av2[k], a0, a1); av[k] = a0 + a1;
    }

    // Publish segment partials (warps 1..3), combine in warp 0 (fixed order)
    if (warp > 0) {
        #pragma unroll
        for (int k = 0; k < RPT; ++k)
            sRow[warp - 1][lane + 32 * k] = make_float4(se[k], au[k], av[k], 0.0f);
    }
    __syncthreads();

    if (warp == 0) {
        float p[8];
        #pragma unroll
        for (int i = 0; i < 8; ++i) p[i] = 0.0f;

        #pragma unroll
        for (int k = 0; k < RPT; ++k) {
            float sek = se[k], auk = au[k], avk = av[k];
            #pragma unroll
            for (int q = 0; q < MSPLIT - 1; ++q) {   // fixed order seg1,2,3
                const float4 f = sRow[q][lane + 32 * k];
                sek += f.x; auk += f.y; avk += f.z;
            }
            const float KINV = 0.34657359027997264f; // ln(2)/2 (undo folded 2*log2e)
            const float inv = KINV / sek;
            const float tcx = auk * inv;
            const float tcy = avk * inv;
            // fixed-order accumulation over k
            p[0] += sx[k];        p[1] += sy[k];
            p[2] += tcx;          p[3] += tcy;
            p[4] += sx[k] * tcx;  p[5] += sx[k] * tcy;
            p[6] += sy[k] * tcx;  p[7] += sy[k] * tcy;
        }

        // Deterministic warp butterfly
        #pragma unroll
        for (int off = 16; off; off >>= 1)
            #pragma unroll
            for (int i = 0; i < 8; ++i)
                p[i] += __shfl_xor_sync(0xFFFFFFFFu, p[i], off);

        if (lane == 0) {
            #pragma unroll
            for (int i = 0; i < 8; ++i) g_part[b][chunk][i] = p[i];
        }
    }
}

// ---------------------------------------------------------------------------
// Per-iteration update: reduce 16 chunk partials, closed-form 2x2 SVD
// (polar factor of H^T), compose transform. grid = BB x 32 threads.
// ---------------------------------------------------------------------------
__global__ void icp_update_kernel(float* __restrict__ out, int final_iter) {
    const int b = blockIdx.x;
    const int t = threadIdx.x;

    float p[8];
    #pragma unroll
    for (int k = 0; k < 8; ++k) p[k] = (t < CHUNKS) ? g_part[b][t][k] : 0.0f;
    #pragma unroll
    for (int off = 16; off; off >>= 1)
        #pragma unroll
        for (int k = 0; k < 8; ++k)
            p[k] += __shfl_xor_sync(0xFFFFFFFFu, p[k], off);

    if (t == 0) {
        const float invN = 1.0f / (float)NN;
        const float csx = p[0] * invN, csy = p[1] * invN;
        const float ctx = p[2] * invN, cty = p[3] * invN;

        const float h00 = p[4] - p[0] * p[2] * invN;
        const float h01 = p[5] - p[0] * p[3] * invN;
        const float h10 = p[6] - p[1] * p[2] * invN;
        const float h11 = p[7] - p[1] * p[3] * invN;

        // R_delta = V @ U^T (SVD of H) == orthogonal polar factor of H^T.
        const float E  = 0.5f * (h00 + h11);
        const float F  = 0.5f * (h00 - h11);
        const float G  = 0.5f * (h01 + h10);
        const float Hh = 0.5f * (h01 - h10);
        const float det = h00 * h11 - h01 * h10;

        float r00, r01, r10, r11;
        if (det >= 0.0f) {           // rotation branch
            float iq = rsqrtf(E * E + Hh * Hh);
            r00 =  E * iq;  r01 = -Hh * iq;
            r10 = Hh * iq;  r11 =  E * iq;
        } else {                      // reflection branch
            float ir = rsqrtf(F * F + G * G);
            r00 =  F * ir;  r01 =  G * ir;
            r10 =  G * ir;  r11 = -F * ir;
        }

        const float ih = rsqrtf(r00 * r00 + r10 * r10);
        const float cD = r00 * ih;
        const float sD = r10 * ih;
        const float tDx = ctx - (r00 * csx + r01 * csy);
        const float tDy = cty - (r10 * csx + r11 * csy);

        const float c  = g_T[b][0], s  = g_T[b][1];
        const float tx = g_T[b][2], ty = g_T[b][3];
        const float c2  = cD * c - sD * s;
        const float s2  = sD * c + cD * s;
        const float tx2 = cD * tx - sD * ty + tDx;
        const float ty2 = sD * tx + cD * ty + tDy;
        g_T[b][0] = c2; g_T[b][1] = s2; g_T[b][2] = tx2; g_T[b][3] = ty2;

        if (final_iter) {
            out[b * 3 + 0] = atan2f(s2, c2);
            out[b * 3 + 1] = tx2;
            out[b * 3 + 2] = ty2;
        }
    }
}

// ---------------------------------------------------------------------------
extern "C" void kernel_launch(void* const* d_in, const int* in_sizes, int n_in,
                              void* d_out, int out_size) {
    const float* source = (const float*)d_in[0];   // (32, 2048, 2)
    const float* target = (const float*)d_in[1];   // (32, 2048, 2)
    const float* init_t = (const float*)d_in[2];   // (32, 3)
    float* out = (float*)d_out;                    // (32, 3)

    icp_init_kernel<<<(BB * NPAIR + 255) / 256, 256>>>(target, init_t);
    for (int it = 0; it < ITERS; ++it) {
        icp_iter_kernel<<<BB * CHUNKS, TPB>>>(source);
        icp_update_kernel<<<BB, 32>>>(out, it == ITERS - 1 ? 1 : 0);
    }
}

// round 7
// speedup vs baseline: 1.8463x; 1.0820x over previous
#include <cuda_runtime.h>
#include <math.h>

// DifferentiableICP: B=32, N=M=2048, 5 soft-ICP iterations.
// R6: MSPLIT 4->8 (TPB 256): doubles chip warps 2048->4096 (~7/SMSP) while
//     keeping RPT=4 register-tile reuse (3 LDS per 4 row-pairs). Target: pin
//     MUFU.EX2 at its rt-8 floor (~30us/iter = 57k cyc).
// Layout: warp w == M-segment w (uniform LDS -> broadcast), lane l owns rows
//         {l, l+32, l+64, l+96} of the CTA's 128-row chunk.

#define BB 32
#define NN 2048
#define MM 2048
#define ITERS 5
#define CHUNKS 16                    // CTAs per batch
#define ROWS_PER_CTA (NN / CHUNKS)   // 128
#define RPT 4                        // rows per thread
#define MSPLIT 8                     // warps per CTA == M segments
#define TPB (32 * MSPLIT)            // 256
#define NPAIR (MM / 2)               // 1024 packed target pairs
#define SEGPAIRS (NPAIR / MSPLIT)    // 128 pairs per segment

typedef unsigned long long ull;

// Scratch (allocation-free rule: __device__ globals)
__device__ ull   g_u2[BB][NPAIR];   // packed (2*log2e*tx) pairs
__device__ ull   g_v2[BB][NPAIR];   // packed (2*log2e*ty) pairs
__device__ ull   g_w2[BB][NPAIR];   // packed (-log2e*|t|^2) pairs
__device__ float g_T[BB][4];        // (cos, sin, tx, ty)
__device__ float g_part[BB][CHUNKS][8];

// ---- packed f32x2 helpers (PTX-only; ptxas never auto-fuses FFMA2) --------
__device__ __forceinline__ ull fma2(ull a, ull b, ull c) {
    ull d; asm("fma.rn.f32x2 %0, %1, %2, %3;" : "=l"(d) : "l"(a), "l"(b), "l"(c));
    return d;
}
__device__ __forceinline__ ull add2(ull a, ull b) {
    ull d; asm("add.rn.f32x2 %0, %1, %2;" : "=l"(d) : "l"(a), "l"(b));
    return d;
}
__device__ __forceinline__ ull pack2(float lo, float hi) {
    ull d; asm("mov.b64 %0, {%1, %2};" : "=l"(d) : "f"(lo), "f"(hi));
    return d;
}
__device__ __forceinline__ void unpack2(ull v, float& lo, float& hi) {
    asm("mov.b64 {%0, %1}, %2;" : "=f"(lo), "=f"(hi) : "l"(v));
}
__device__ __forceinline__ float ex2f(float x) {
    float e; asm("ex2.approx.ftz.f32 %0, %1;" : "=f"(e) : "f"(x));
    return e;
}

// ---------------------------------------------------------------------------
// Init: paired, log2e-folded target constants + initial transform.
// ---------------------------------------------------------------------------
__global__ void icp_init_kernel(const float* __restrict__ target,
                                const float* __restrict__ init_t) {
    int g = blockIdx.x * blockDim.x + threadIdx.x;
    if (g < BB * NPAIR) {
        int b = g >> 10, p = g & (NPAIR - 1);
        float4 f = reinterpret_cast<const float4*>(target)[(size_t)b * NPAIR + p];
        const float L2E = 1.4426950408889634f;
        g_u2[b][p] = pack2(2.0f * L2E * f.x, 2.0f * L2E * f.z);
        g_v2[b][p] = pack2(2.0f * L2E * f.y, 2.0f * L2E * f.w);
        g_w2[b][p] = pack2(-L2E * (f.x * f.x + f.y * f.y),
                           -L2E * (f.z * f.z + f.w * f.w));
    }
    if (g < BB) {
        float th = init_t[g * 3 + 0];
        g_T[g][0] = cosf(th);
        g_T[g][1] = sinf(th);
        g_T[g][2] = init_t[g * 3 + 1];
        g_T[g][3] = init_t[g * 3 + 2];
    }
}

// ---------------------------------------------------------------------------
// Main per-iteration kernel. grid = BB*CHUNKS = 512 CTAs, block = 256.
// ---------------------------------------------------------------------------
__global__ void __launch_bounds__(TPB)
icp_iter_kernel(const float* __restrict__ source) {
    __shared__ ull    sU[NPAIR], sV[NPAIR], sW[NPAIR];   // 24 KB
    __shared__ float4 sRow[MSPLIT - 1][ROWS_PER_CTA];    // 14 KB seg partials

    const int b     = blockIdx.x >> 4;
    const int chunk = blockIdx.x & 15;
    const int tid   = threadIdx.x;
    const int lane  = tid & 31;
    const int warp  = tid >> 5;          // == M-segment

    // Stage paired target constants (coalesced 8B loads)
    for (int i = tid; i < NPAIR; i += TPB) {
        sU[i] = g_u2[b][i];
        sV[i] = g_v2[b][i];
        sW[i] = g_w2[b][i];
    }

    // Current transform (uniform)
    const float c  = g_T[b][0];
    const float s  = g_T[b][1];
    const float tx = g_T[b][2];
    const float ty = g_T[b][3];

    // st = R*source + t for this thread's 4 rows
    float sx[RPT], sy[RPT];
    ull sx2[RPT], sy2[RPT];
    #pragma unroll
    for (int k = 0; k < RPT; ++k) {
        const int row = chunk * ROWS_PER_CTA + lane + 32 * k;
        const float2 sv = reinterpret_cast<const float2*>(source)[(size_t)b * NN + row];
        sx[k] = c * sv.x - s * sv.y + tx;
        sy[k] = s * sv.x + c * sv.y + ty;
        sx2[k] = pack2(sx[k], sx[k]);
        sy2[k] = pack2(sy[k], sy[k]);
    }

    __syncthreads();

    // Packed single-pass softmax-weighted sums: 3 LDS amortized over 4 rows.
    ull se2[RPT], au2[RPT], av2[RPT];
    #pragma unroll
    for (int k = 0; k < RPT; ++k) { se2[k] = 0ull; au2[k] = 0ull; av2[k] = 0ull; }

    const int p0 = warp * SEGPAIRS;
    #pragma unroll 2
    for (int p = p0; p < p0 + SEGPAIRS; ++p) {
        const ull u2 = sU[p];
        const ull v2 = sV[p];
        const ull w2 = sW[p];
        #pragma unroll
        for (int k = 0; k < RPT; ++k) {
            ull y2 = fma2(sx2[k], u2, w2);
            y2 = fma2(sy2[k], v2, y2);
            float y0, y1; unpack2(y2, y0, y1);
            const ull e2 = pack2(ex2f(y0), ex2f(y1));
            se2[k] = add2(se2[k], e2);
            au2[k] = fma2(e2, u2, au2[k]);
            av2[k] = fma2(e2, v2, av2[k]);
        }
    }

    // Horizontal add of the packed halves (fixed order: lo + hi)
    float se[RPT], au[RPT], av[RPT];
    #pragma unroll
    for (int k = 0; k < RPT; ++k) {
        float a0, a1;
        unpack2(se2[k], a0, a1); se[k] = a0 + a1;
        unpack2(au2[k], a0, a1); au[k] = a0 + a1;
        unpack2(av2[k], a0, a1); av[k] = a0 + a1;
    }

    // Publish segment partials (warps 1..7), combine in warp 0 (fixed order)
    if (warp > 0) {
        #pragma unroll
        for (int k = 0; k < RPT; ++k)
            sRow[warp - 1][lane + 32 * k] = make_float4(se[k], au[k], av[k], 0.0f);
    }
    __syncthreads();

    if (warp == 0) {
        float p[8];
        #pragma unroll
        for (int i = 0; i < 8; ++i) p[i] = 0.0f;

        #pragma unroll
        for (int k = 0; k < RPT; ++k) {
            float sek = se[k], auk = au[k], avk = av[k];
            #pragma unroll
            for (int q = 0; q < MSPLIT - 1; ++q) {   // fixed order seg1..7
                const float4 f = sRow[q][lane + 32 * k];
                sek += f.x; auk += f.y; avk += f.z;
            }
            const float KINV = 0.34657359027997264f; // ln(2)/2 (undo folded 2*log2e)
            const float inv = KINV / sek;
            const float tcx = auk * inv;
            const float tcy = avk * inv;
            // fixed-order accumulation over k
            p[0] += sx[k];        p[1] += sy[k];
            p[2] += tcx;          p[3] += tcy;
            p[4] += sx[k] * tcx;  p[5] += sx[k] * tcy;
            p[6] += sy[k] * tcx;  p[7] += sy[k] * tcy;
        }

        // Deterministic warp butterfly
        #pragma unroll
        for (int off = 16; off; off >>= 1)
            #pragma unroll
            for (int i = 0; i < 8; ++i)
                p[i] += __shfl_xor_sync(0xFFFFFFFFu, p[i], off);

        if (lane == 0) {
            #pragma unroll
            for (int i = 0; i < 8; ++i) g_part[b][chunk][i] = p[i];
        }
    }
}

// ---------------------------------------------------------------------------
// Per-iteration update: reduce 16 chunk partials, closed-form 2x2 SVD
// (polar factor of H^T), compose transform. grid = BB x 32 threads.
// ---------------------------------------------------------------------------
__global__ void icp_update_kernel(float* __restrict__ out, int final_iter) {
    const int b = blockIdx.x;
    const int t = threadIdx.x;

    float p[8];
    #pragma unroll
    for (int k = 0; k < 8; ++k) p[k] = (t < CHUNKS) ? g_part[b][t][k] : 0.0f;
    #pragma unroll
    for (int off = 16; off; off >>= 1)
        #pragma unroll
        for (int k = 0; k < 8; ++k)
            p[k] += __shfl_xor_sync(0xFFFFFFFFu, p[k], off);

    if (t == 0) {
        const float invN = 1.0f / (float)NN;
        const float csx = p[0] * invN, csy = p[1] * invN;
        const float ctx = p[2] * invN, cty = p[3] * invN;

        const float h00 = p[4] - p[0] * p[2] * invN;
        const float h01 = p[5] - p[0] * p[3] * invN;
        const float h10 = p[6] - p[1] * p[2] * invN;
        const float h11 = p[7] - p[1] * p[3] * invN;

        // R_delta = V @ U^T (SVD of H) == orthogonal polar factor of H^T.
        const float E  = 0.5f * (h00 + h11);
        const float F  = 0.5f * (h00 - h11);
        const float G  = 0.5f * (h01 + h10);
        const float Hh = 0.5f * (h01 - h10);
        const float det = h00 * h11 - h01 * h10;

        float r00, r01, r10, r11;
        if (det >= 0.0f) {           // rotation branch
            float iq = rsqrtf(E * E + Hh * Hh);
            r00 =  E * iq;  r01 = -Hh * iq;
            r10 = Hh * iq;  r11 =  E * iq;
        } else {                      // reflection branch
            float ir = rsqrtf(F * F + G * G);
            r00 =  F * ir;  r01 =  G * ir;
            r10 =  G * ir;  r11 = -F * ir;
        }

        const float ih = rsqrtf(r00 * r00 + r10 * r10);
        const float cD = r00 * ih;
        const float sD = r10 * ih;
        const float tDx = ctx - (r00 * csx + r01 * csy);
        const float tDy = cty - (r10 * csx + r11 * csy);

        const float c  = g_T[b][0], s  = g_T[b][1];
        const float tx = g_T[b][2], ty = g_T[b][3];
        const float c2  = cD * c - sD * s;
        const float s2  = sD * c + cD * s;
        const float tx2 = cD * tx - sD * ty + tDx;
        const float ty2 = sD * tx + cD * ty + tDy;
        g_T[b][0] = c2; g_T[b][1] = s2; g_T[b][2] = tx2; g_T[b][3] = ty2;

        if (final_iter) {
            out[b * 3 + 0] = atan2f(s2, c2);
            out[b * 3 + 1] = tx2;
            out[b * 3 + 2] = ty2;
        }
    }
}

// ---------------------------------------------------------------------------
extern "C" void kernel_launch(void* const* d_in, const int* in_sizes, int n_in,
                              void* d_out, int out_size) {
    const float* source = (const float*)d_in[0];   // (32, 2048, 2)
    const float* target = (const float*)d_in[1];   // (32, 2048, 2)
    const float* init_t = (const float*)d_in[2];   // (32, 3)
    float* out = (float*)d_out;                    // (32, 3)

    icp_init_kernel<<<(BB * NPAIR + 255) / 256, 256>>>(target, init_t);
    for (int it = 0; it < ITERS; ++it) {
        icp_iter_kernel<<<BB * CHUNKS, TPB>>>(source);
        icp_update_kernel<<<BB, 32>>>(out, it == ITERS - 1 ? 1 : 0);
    }
}

// round 8
// speedup vs baseline: 2.0909x; 1.1325x over previous
#include <cuda_runtime.h>
#include <math.h>

// DifferentiableICP: B=32, N=M=2048, 5 soft-ICP iterations.
// R7: kill wave quantization. grid 512->1024 CTAs (64 rows each, TPB=128,
//     MSPLIT=4, RPT=2): 8 CTAs/SM resident -> single wave, per-SM work
//     imbalance 16% -> 1.2%. Also fuse (u,v) into one ulonglong2 so the
//     mainloop does 2 LDS/pair (LDS.128 + LDS.64) instead of 3.
// MUFU.EX2 floor: 4 exps/pair * rt8 = 32 cyc/pair/warp -> ~30us/iter chip-wide.

#define BB 32
#define NN 2048
#define MM 2048
#define ITERS 5
#define CHUNKS 32                    // CTAs per batch
#define ROWS_PER_CTA (NN / CHUNKS)   // 64
#define RPT 2                        // rows per thread
#define MSPLIT 4                     // warps per CTA == M segments
#define TPB (32 * MSPLIT)            // 128
#define NPAIR (MM / 2)               // 1024 packed target pairs
#define SEGPAIRS (NPAIR / MSPLIT)    // 256 pairs per segment

typedef unsigned long long ull;

// Scratch (allocation-free rule: __device__ globals)
__device__ ulonglong2 g_uv2[BB][NPAIR]; // packed ((2L2E*tx pair),(2L2E*ty pair))
__device__ ull        g_w2[BB][NPAIR];  // packed (-L2E*|t|^2) pairs
__device__ float      g_T[BB][4];       // (cos, sin, tx, ty)
__device__ float      g_part[BB][CHUNKS][8];

// ---- packed f32x2 helpers (PTX-only; ptxas never auto-fuses FFMA2) --------
__device__ __forceinline__ ull fma2(ull a, ull b, ull c) {
    ull d; asm("fma.rn.f32x2 %0, %1, %2, %3;" : "=l"(d) : "l"(a), "l"(b), "l"(c));
    return d;
}
__device__ __forceinline__ ull add2(ull a, ull b) {
    ull d; asm("add.rn.f32x2 %0, %1, %2;" : "=l"(d) : "l"(a), "l"(b));
    return d;
}
__device__ __forceinline__ ull pack2(float lo, float hi) {
    ull d; asm("mov.b64 %0, {%1, %2};" : "=l"(d) : "f"(lo), "f"(hi));
    return d;
}
__device__ __forceinline__ void unpack2(ull v, float& lo, float& hi) {
    asm("mov.b64 {%0, %1}, %2;" : "=f"(lo), "=f"(hi) : "l"(v));
}
__device__ __forceinline__ float ex2f(float x) {
    float e; asm("ex2.approx.ftz.f32 %0, %1;" : "=f"(e) : "f"(x));
    return e;
}

// ---------------------------------------------------------------------------
// Init: paired, log2e-folded target constants + initial transform.
// ---------------------------------------------------------------------------
__global__ void icp_init_kernel(const float* __restrict__ target,
                                const float* __restrict__ init_t) {
    int g = blockIdx.x * blockDim.x + threadIdx.x;
    if (g < BB * NPAIR) {
        int b = g >> 10, p = g & (NPAIR - 1);
        float4 f = reinterpret_cast<const float4*>(target)[(size_t)b * NPAIR + p];
        const float L2E = 1.4426950408889634f;
        ulonglong2 uv;
        uv.x = pack2(2.0f * L2E * f.x, 2.0f * L2E * f.z);
        uv.y = pack2(2.0f * L2E * f.y, 2.0f * L2E * f.w);
        g_uv2[b][p] = uv;
        g_w2[b][p]  = pack2(-L2E * (f.x * f.x + f.y * f.y),
                            -L2E * (f.z * f.z + f.w * f.w));
    }
    if (g < BB) {
        float th = init_t[g * 3 + 0];
        g_T[g][0] = cosf(th);
        g_T[g][1] = sinf(th);
        g_T[g][2] = init_t[g * 3 + 1];
        g_T[g][3] = init_t[g * 3 + 2];
    }
}

// ---------------------------------------------------------------------------
// Main per-iteration kernel. grid = BB*CHUNKS = 1024 CTAs, block = 128.
// Warp w == M-segment w (uniform LDS -> broadcast). Lane l owns rows
// {l, l+32} of the CTA's 64-row chunk.
// ---------------------------------------------------------------------------
__global__ void __launch_bounds__(TPB, 8)
icp_iter_kernel(const float* __restrict__ source) {
    __shared__ ulonglong2 sUV[NPAIR];                  // 16 KB
    __shared__ ull        sW[NPAIR];                   // 8 KB
    __shared__ float4     sRow[MSPLIT - 1][ROWS_PER_CTA]; // 3 KB seg partials

    const int b     = blockIdx.x >> 5;
    const int chunk = blockIdx.x & 31;
    const int tid   = threadIdx.x;
    const int lane  = tid & 31;
    const int warp  = tid >> 5;          // == M-segment

    // Stage paired target constants (coalesced 16B/8B loads)
    for (int i = tid; i < NPAIR; i += TPB) {
        sUV[i] = g_uv2[b][i];
        sW[i]  = g_w2[b][i];
    }

    // Current transform (uniform)
    const float c  = g_T[b][0];
    const float s  = g_T[b][1];
    const float tx = g_T[b][2];
    const float ty = g_T[b][3];

    // st = R*source + t for this thread's 2 rows
    float sx[RPT], sy[RPT];
    ull sx2[RPT], sy2[RPT];
    #pragma unroll
    for (int k = 0; k < RPT; ++k) {
        const int row = chunk * ROWS_PER_CTA + lane + 32 * k;
        const float2 sv = reinterpret_cast<const float2*>(source)[(size_t)b * NN + row];
        sx[k] = c * sv.x - s * sv.y + tx;
        sy[k] = s * sv.x + c * sv.y + ty;
        sx2[k] = pack2(sx[k], sx[k]);
        sy2[k] = pack2(sy[k], sy[k]);
    }

    __syncthreads();

    // Packed single-pass softmax-weighted sums: 2 LDS per pair, reused x2 rows.
    ull se2[RPT], au2[RPT], av2[RPT];
    #pragma unroll
    for (int k = 0; k < RPT; ++k) { se2[k] = 0ull; au2[k] = 0ull; av2[k] = 0ull; }

    const int p0 = warp * SEGPAIRS;
    #pragma unroll 4
    for (int p = p0; p < p0 + SEGPAIRS; ++p) {
        const ulonglong2 uv = sUV[p];
        const ull u2 = uv.x;
        const ull v2 = uv.y;
        const ull w2 = sW[p];
        #pragma unroll
        for (int k = 0; k < RPT; ++k) {
            ull y2 = fma2(sx2[k], u2, w2);
            y2 = fma2(sy2[k], v2, y2);
            float y0, y1; unpack2(y2, y0, y1);
            const ull e2 = pack2(ex2f(y0), ex2f(y1));
            se2[k] = add2(se2[k], e2);
            au2[k] = fma2(e2, u2, au2[k]);
            av2[k] = fma2(e2, v2, av2[k]);
        }
    }

    // Horizontal add of the packed halves (fixed order: lo + hi)
    float se[RPT], au[RPT], av[RPT];
    #pragma unroll
    for (int k = 0; k < RPT; ++k) {
        float a0, a1;
        unpack2(se2[k], a0, a1); se[k] = a0 + a1;
        unpack2(au2[k], a0, a1); au[k] = a0 + a1;
        unpack2(av2[k], a0, a1); av[k] = a0 + a1;
    }

    // Publish segment partials (warps 1..3), combine in warp 0 (fixed order)
    if (warp > 0) {
        #pragma unroll
        for (int k = 0; k < RPT; ++k)
            sRow[warp - 1][lane + 32 * k] = make_float4(se[k], au[k], av[k], 0.0f);
    }
    __syncthreads();

    if (warp == 0) {
        float p[8];
        #pragma unroll
        for (int i = 0; i < 8; ++i) p[i] = 0.0f;

        #pragma unroll
        for (int k = 0; k < RPT; ++k) {
            float sek = se[k], auk = au[k], avk = av[k];
            #pragma unroll
            for (int q = 0; q < MSPLIT - 1; ++q) {   // fixed order seg1..3
                const float4 f = sRow[q][lane + 32 * k];
                sek += f.x; auk += f.y; avk += f.z;
            }
            const float KINV = 0.34657359027997264f; // ln(2)/2 (undo folded 2*log2e)
            const float inv = KINV / sek;
            const float tcx = auk * inv;
            const float tcy = avk * inv;
            // fixed-order accumulation over k
            p[0] += sx[k];        p[1] += sy[k];
            p[2] += tcx;          p[3] += tcy;
            p[4] += sx[k] * tcx;  p[5] += sx[k] * tcy;
            p[6] += sy[k] * tcx;  p[7] += sy[k] * tcy;
        }

        // Deterministic warp butterfly
        #pragma unroll
        for (int off = 16; off; off >>= 1)
            #pragma unroll
            for (int i = 0; i < 8; ++i)
                p[i] += __shfl_xor_sync(0xFFFFFFFFu, p[i], off);

        if (lane == 0) {
            #pragma unroll
            for (int i = 0; i < 8; ++i) g_part[b][chunk][i] = p[i];
        }
    }
}

// ---------------------------------------------------------------------------
// Per-iteration update: reduce 32 chunk partials, closed-form 2x2 SVD
// (polar factor of H^T), compose transform. grid = BB x 32 threads.
// ---------------------------------------------------------------------------
__global__ void icp_update_kernel(float* __restrict__ out, int final_iter) {
    const int b = blockIdx.x;
    const int t = threadIdx.x;

    float p[8];
    #pragma unroll
    for (int k = 0; k < 8; ++k) p[k] = g_part[b][t][k];
    #pragma unroll
    for (int off = 16; off; off >>= 1)
        #pragma unroll
        for (int k = 0; k < 8; ++k)
            p[k] += __shfl_xor_sync(0xFFFFFFFFu, p[k], off);

    if (t == 0) {
        const float invN = 1.0f / (float)NN;
        const float csx = p[0] * invN, csy = p[1] * invN;
        const float ctx = p[2] * invN, cty = p[3] * invN;

        const float h00 = p[4] - p[0] * p[2] * invN;
        const float h01 = p[5] - p[0] * p[3] * invN;
        const float h10 = p[6] - p[1] * p[2] * invN;
        const float h11 = p[7] - p[1] * p[3] * invN;

        // R_delta = V @ U^T (SVD of H) == orthogonal polar factor of H^T.
        const float E  = 0.5f * (h00 + h11);
        const float F  = 0.5f * (h00 - h11);
        const float G  = 0.5f * (h01 + h10);
        const float Hh = 0.5f * (h01 - h10);
        const float det = h00 * h11 - h01 * h10;

        float r00, r01, r10, r11;
        if (det >= 0.0f) {           // rotation branch
            float iq = rsqrtf(E * E + Hh * Hh);
            r00 =  E * iq;  r01 = -Hh * iq;
            r10 = Hh * iq;  r11 =  E * iq;
        } else {                      // reflection branch
            float ir = rsqrtf(F * F + G * G);
            r00 =  F * ir;  r01 =  G * ir;
            r10 =  G * ir;  r11 = -F * ir;
        }

        const float ih = rsqrtf(r00 * r00 + r10 * r10);
        const float cD = r00 * ih;
        const float sD = r10 * ih;
        const float tDx = ctx - (r00 * csx + r01 * csy);
        const float tDy = cty - (r10 * csx + r11 * csy);

        const float c  = g_T[b][0], s  = g_T[b][1];
        const float tx = g_T[b][2], ty = g_T[b][3];
        const float c2  = cD * c - sD * s;
        const float s2  = sD * c + cD * s;
        const float tx2 = cD * tx - sD * ty + tDx;
        const float ty2 = sD * tx + cD * ty + tDy;
        g_T[b][0] = c2; g_T[b][1] = s2; g_T[b][2] = tx2; g_T[b][3] = ty2;

        if (final_iter) {
            out[b * 3 + 0] = atan2f(s2, c2);
            out[b * 3 + 1] = tx2;
            out[b * 3 + 2] = ty2;
        }
    }
}

// ---------------------------------------------------------------------------
extern "C" void kernel_launch(void* const* d_in, const int* in_sizes, int n_in,
                              void* d_out, int out_size) {
    const float* source = (const float*)d_in[0];   // (32, 2048, 2)
    const float* target = (const float*)d_in[1];   // (32, 2048, 2)
    const float* init_t = (const float*)d_in[2];   // (32, 3)
    float* out = (float*)d_out;                    // (32, 3)

    icp_init_kernel<<<(BB * NPAIR + 255) / 256, 256>>>(target, init_t);
    for (int it = 0; it < ITERS; ++it) {
        icp_iter_kernel<<<BB * CHUNKS, TPB>>>(source);
        icp_update_kernel<<<BB, 32>>>(out, it == ITERS - 1 ? 1 : 0);
    }
}